// round 17
// baseline (speedup 1.0000x reference)
#include <cuda_runtime.h>
#include <cuda_bf16.h>
#include <cstdint>
#include <cstddef>

// Problem constants
#define Bm   64
#define Sk   720
#define Cc   321
#define Pp   336
#define HALO 12

// Tiling
#define NT     112
#define KT     48
#define NTILES 15
#define NCHUNK 18        // (KT+2*HALO)/4 fp32 chunks per raw-W row
#define THREADS 256      // 8 warps: mw = wid&3 (16 M rows), ng = wid>>2 (N half)

// bf16 tile row stride: 112 B (conflict-free ldmatrix)
#define BROW 112
// raw W fp32 row stride: 304 B (76 words: 16B-strided reads conflict-free)
#define WROW 304

// smem layout (bytes) — single-stage everything: 107,520 B -> 2 CTAs/SM
#define OFF_AH 0                      // A hi: 64 x 112B = 7168
#define OFF_AL 7168                   // A lo
#define OFF_BH 14336                  // B hi: 112 x 112B = 12544
#define OFF_BL 26880                  // B lo
#define OFF_WR 39424                  // raw W_res ext: 112 x 304B = 34048
#define OFF_WT 73472                  // raw W_trd ext
#define SMEM_TOTAL 107520

// x split into bf16 hi/lo, layout [c][b][s]
__device__ __nv_bfloat16 g_xhi[(size_t)Cc * Bm * Sk];
__device__ __nv_bfloat16 g_xlo[(size_t)Cc * Bm * Sk];

__device__ __forceinline__ unsigned smem_u32(const void* p) {
    return (unsigned)__cvta_generic_to_shared(p);
}
__device__ __forceinline__ void cp16(unsigned dst, const void* src, unsigned sz) {
    asm volatile("cp.async.ca.shared.global [%0], [%1], 16, %2;"
                 :: "r"(dst), "l"(src), "r"(sz));
}
#define LDSM4(r, addr) \
    asm volatile("ldmatrix.sync.aligned.m8n8.x4.shared.b16 {%0,%1,%2,%3}, [%4];" \
        : "=r"((r)[0]), "=r"((r)[1]), "=r"((r)[2]), "=r"((r)[3]) : "r"(addr))

__device__ __forceinline__ void mma_bf16(float* c, const unsigned* a,
                                         unsigned b0, unsigned b1) {
    asm volatile(
        "mma.sync.aligned.m16n8k16.row.col.f32.bf16.bf16.f32 "
        "{%0,%1,%2,%3}, {%4,%5,%6,%7}, {%8,%9}, {%0,%1,%2,%3};"
        : "+f"(c[0]), "+f"(c[1]), "+f"(c[2]), "+f"(c[3])
        : "r"(a[0]), "r"(a[1]), "r"(a[2]), "r"(a[3]), "r"(b0), "r"(b1));
}

// ---------------------------------------------------------------------------
// Kernel 1: x [b][s][c] fp32 -> g_xhi/g_xlo [c][b][s] bf16 (2-term split)
// ---------------------------------------------------------------------------
__global__ void transpose_split_kernel(const float* __restrict__ x) {
    __shared__ float tile[32][33];
    int b  = blockIdx.z;
    int c0 = blockIdx.x * 32;
    int s0 = blockIdx.y * 32;
    int tx = threadIdx.x, ty = threadIdx.y;

    #pragma unroll
    for (int i = 0; i < 4; i++) {
        int s = s0 + ty + 8*i, c = c0 + tx;
        if (s < Sk && c < Cc)
            tile[ty + 8*i][tx] = x[((size_t)b * Sk + s) * Cc + c];
    }
    __syncthreads();
    #pragma unroll
    for (int i = 0; i < 4; i++) {
        int c = c0 + ty + 8*i, s = s0 + tx;
        if (c < Cc && s < Sk) {
            float v = tile[tx][ty + 8*i];
            __nv_bfloat16 h = __float2bfloat16(v);
            __nv_bfloat16 l = __float2bfloat16(v - __bfloat162float(h));
            size_t o = ((size_t)c * Bm + b) * Sk + s;
            g_xhi[o] = h;
            g_xlo[o] = l;
        }
    }
}

// ---------------------------------------------------------------------------
// Kernel 2: folded GEMM on mma.sync, 2 CTAs/SM, intra-tile overlap.
//   D = A_hi*B_hi + A_hi*B_lo + A_lo*B_hi
//   W_eff[p,s] = W_res[p,s] + (1/25)*sum_{t in [s-12,s+12] ∩ [0,Sk)} (W_trd-W_res)[p,t]
// Per tile: wait -> sync -> A-LDSM (regs) + build -> sync ->
//           issue loads(it+1) [sA & sW now dead] -> MMA (register A).
// ---------------------------------------------------------------------------
__global__ __launch_bounds__(THREADS, 2)
void dlinear_hmma(const float* __restrict__ Wres, const float* __restrict__ bres,
                  const float* __restrict__ Wtrd, const float* __restrict__ btrd,
                  float* __restrict__ out)
{
    extern __shared__ char smem[];
    const unsigned sb = smem_u32(smem);
    const int tid  = threadIdx.x;
    const int wid  = tid >> 5;
    const int lane = tid & 31;
    const int mw   = wid & 3;     // 16 M rows each
    const int ng   = wid >> 2;    // 0: jp 0..3, 1: jp 4..6
    const int jp0  = ng ? 4 : 0;
    const int njp  = ng ? 3 : 4;

    const int c  = blockIdx.y;
    const int n0 = blockIdx.x * NT;

    const float* wr = Wres + ((size_t)c * Pp + n0) * Sk;
    const float* wt = Wtrd + ((size_t)c * Pp + n0) * Sk;
    const __nv_bfloat16* xh = g_xhi + (size_t)c * Bm * Sk;
    const __nv_bfloat16* xl = g_xlo + (size_t)c * Bm * Sk;

    float acc[8][4];
    #pragma unroll
    for (int j = 0; j < 8; j++)
        #pragma unroll
        for (int i = 0; i < 4; i++) acc[j][i] = 0.f;

    // ldmatrix lane address bases (verified mapping)
    const unsigned aOff = (unsigned)((16 * mw + (lane & 15)) * BROW + (lane >> 4) * 16);
    const unsigned bOff = (unsigned)((lane & 7) * BROW + ((lane >> 3) & 1) * 16
                                     + ((lane >> 4) & 1) * (8 * BROW));

    // ---- tile-load issuer: one commit group per tile ----
    auto issue_loads = [&](int it) {
        const int k0 = it * KT;
        // A: 2 parts x 64 rows x 6 chunks = 768 = 256*3
        #pragma unroll
        for (int j = 0; j < 3; j++) {
            int idx  = tid + THREADS * j;
            int part = idx / 384;
            int r    = idx - part * 384;
            int m    = r / 6, ci = r % 6;
            const __nv_bfloat16* src = (part ? xl : xh) + (size_t)m * Sk + k0 + ci * 8;
            cp16(sb + (part ? OFF_AL : OFF_AH) + (unsigned)(m * BROW + ci * 16), src, 16u);
        }
        // raw W ext: 2 arrays x 112 rows x 18 chunks = 4032 (< 256*16)
        #pragma unroll
        for (int j = 0; j < 16; j++) {
            int idx = tid + THREADS * j;
            if (idx < 2 * NT * NCHUNK) {
                int t   = idx / (NT * NCHUNK);
                int rem = idx - t * (NT * NCHUNK);
                int n   = rem / NCHUNK, ci = rem % NCHUNK;
                int s0  = k0 - HALO + ci * 4;
                unsigned ok = (s0 >= 0 && s0 <= Sk - 4) ? 16u : 0u;
                int s0c = s0 < 0 ? 0 : (s0 > Sk - 4 ? Sk - 4 : s0);
                const float* src = (t ? wt : wr) + (size_t)n * Sk + s0c;
                cp16(sb + (t ? OFF_WT : OFF_WR) + (unsigned)(n * WROW + ci * 16), src, ok);
            }
        }
        asm volatile("cp.async.commit_group;" ::: "memory");
    };

    issue_loads(0);

    for (int it = 0; it < NTILES; it++) {
        asm volatile("cp.async.wait_group 0;" ::: "memory");
        __syncthreads();   // tile it landed; also fences last tile's B reads

        // ---- hoist A fragments for all 3 k-chunks into registers ----
        unsigned ah[3][4], al[3][4];
        #pragma unroll
        for (int kc = 0; kc < 3; kc++) {
            LDSM4(ah[kc], sb + OFF_AH + aOff + kc * 32);
            LDSM4(al[kc], sb + OFF_AL + aOff + kc * 32);
        }

        // ---- build W_eff: 224 threads, 2 per row (half-rows of 24 k) ----
        if (tid < 2 * NT) {
            const int n  = tid % NT;
            const int h  = tid / NT;
            const int cb = 6 * h;            // ext chunk base; kb = 24h
            const float4* wr4 = (const float4*)(smem + OFF_WR + n * WROW);
            const float4* wt4 = (const float4*)(smem + OFF_WT + n * WROW);
            char* bh = smem + OFF_BH + n * BROW + 48 * h;
            char* bl = smem + OFF_BL + n * BROW + 48 * h;

            float4 dbuf[6];
            float cs = 0.f;
            #pragma unroll
            for (int t = 0; t < 6; t++) {
                float4 a = wr4[cb + t], b = wt4[cb + t];
                float4 d = make_float4(b.x - a.x, b.y - a.y, b.z - a.z, b.w - a.w);
                dbuf[t] = d;
                cs += (d.x + d.y) + (d.z + d.w);
            }
            #pragma unroll
            for (int j = 0; j < 6; j++) {
                float4 a  = wr4[cb + j + 6], b = wt4[cb + j + 6];
                float4 dn = make_float4(b.x - a.x, b.y - a.y, b.z - a.z, b.w - a.w);
                float4 wo = wr4[cb + j + 3];
                float4 d0 = dbuf[j];
                float S0 = cs + dn.x;
                float S1 = S0 + dn.y - d0.x;
                float S2 = S1 + dn.z - d0.y;
                float S3 = S2 + dn.w - d0.z;
                float w0 = wo.x + S0 * (1.0f / 25.0f);
                float w1 = wo.y + S1 * (1.0f / 25.0f);
                float w2 = wo.z + S2 * (1.0f / 25.0f);
                float w3 = wo.w + S3 * (1.0f / 25.0f);

                __nv_bfloat16 h0 = __float2bfloat16(w0), h1 = __float2bfloat16(w1);
                __nv_bfloat16 h2 = __float2bfloat16(w2), h3 = __float2bfloat16(w3);
                __nv_bfloat16 l0 = __float2bfloat16(w0 - __bfloat162float(h0));
                __nv_bfloat16 l1 = __float2bfloat16(w1 - __bfloat162float(h1));
                __nv_bfloat16 l2 = __float2bfloat16(w2 - __bfloat162float(h2));
                __nv_bfloat16 l3 = __float2bfloat16(w3 - __bfloat162float(h3));

                *(unsigned*)(bh + 8 * j) =
                    (unsigned)__bfloat16_as_ushort(h0) | ((unsigned)__bfloat16_as_ushort(h1) << 16);
                *(unsigned*)(bh + 8 * j + 4) =
                    (unsigned)__bfloat16_as_ushort(h2) | ((unsigned)__bfloat16_as_ushort(h3) << 16);
                *(unsigned*)(bl + 8 * j) =
                    (unsigned)__bfloat16_as_ushort(l0) | ((unsigned)__bfloat16_as_ushort(l1) << 16);
                *(unsigned*)(bl + 8 * j + 4) =
                    (unsigned)__bfloat16_as_ushort(l2) | ((unsigned)__bfloat16_as_ushort(l3) << 16);

                cs += ((dn.x + dn.y) + (dn.z + dn.w)) - ((d0.x + d0.y) + (d0.z + d0.w));
                dbuf[j] = dn;
            }
        }
        __syncthreads();   // sB ready; sA (regs hoisted) and raw W now dead

        // ---- prefetch next tile into the now-dead sA/sW during MMA ----
        if (it + 1 < NTILES) issue_loads(it + 1);

        // ---- HMMA phase: register A, smem B ----
        #pragma unroll
        for (int kc = 0; kc < 3; kc++) {
            #pragma unroll
            for (int jpl = 0; jpl < 4; jpl++) {
                if (jpl < njp) {
                    int jp = jp0 + jpl;
                    unsigned bhf[4], blf[4];
                    unsigned bbase = bOff + (unsigned)(jp * 16 * BROW) + kc * 32;
                    LDSM4(bhf, sb + OFF_BH + bbase);
                    LDSM4(blf, sb + OFF_BL + bbase);
                    mma_bf16(acc[2*jpl],     ah[kc], bhf[0], bhf[1]);
                    mma_bf16(acc[2*jpl],     ah[kc], blf[0], blf[1]);
                    mma_bf16(acc[2*jpl],     al[kc], bhf[0], bhf[1]);
                    mma_bf16(acc[2*jpl + 1], ah[kc], bhf[2], bhf[3]);
                    mma_bf16(acc[2*jpl + 1], ah[kc], blf[2], blf[3]);
                    mma_bf16(acc[2*jpl + 1], al[kc], bhf[2], bhf[3]);
                }
            }
        }
        // no sync needed here: next iteration's wait+sync fences sB reuse
    }

    // ---- epilogue: add biases, write out[b][c][p] ----
    const int mlo = 16 * mw + (lane >> 2);
    const int pq  = 2 * (lane & 3);
    const float* br = bres + (size_t)c * Pp + n0;
    const float* bt = btrd + (size_t)c * Pp + n0;
    #pragma unroll
    for (int jpl = 0; jpl < 4; jpl++) {
        if (jpl < njp) {
            #pragma unroll
            for (int t = 0; t < 2; t++) {
                int jg = 2 * (jp0 + jpl) + t;       // global n8 tile 0..13
                int p  = 8 * jg + pq;
                float b0 = br[p] + bt[p];
                float b1 = br[p + 1] + bt[p + 1];
                float* a = acc[2 * jpl + t];
                *(float2*)(out + ((size_t)mlo * Cc + c) * Pp + n0 + p) =
                    make_float2(a[0] + b0, a[1] + b1);
                *(float2*)(out + ((size_t)(mlo + 8) * Cc + c) * Pp + n0 + p) =
                    make_float2(a[2] + b0, a[3] + b1);
            }
        }
    }
}

// ---------------------------------------------------------------------------
extern "C" void kernel_launch(void* const* d_in, const int* in_sizes, int n_in,
                              void* d_out, int out_size) {
    (void)in_sizes; (void)n_in; (void)out_size;
    const float* x    = (const float*)d_in[0];
    const float* Wres = (const float*)d_in[1];
    const float* bres = (const float*)d_in[2];
    const float* Wtrd = (const float*)d_in[3];
    const float* btrd = (const float*)d_in[4];
    float* out = (float*)d_out;

    transpose_split_kernel<<<dim3((Cc + 31) / 32, (Sk + 31) / 32, Bm), dim3(32, 8)>>>(x);

    cudaFuncSetAttribute(dlinear_hmma,
                         cudaFuncAttributeMaxDynamicSharedMemorySize, SMEM_TOTAL);
    dlinear_hmma<<<dim3(Pp / NT, Cc), THREADS, SMEM_TOTAL>>>(Wres, bres, Wtrd, btrd, out);
}